// round 14
// baseline (speedup 1.0000x reference)
#include <cuda_runtime.h>

#define XNS 32
#define XNC 16
#define XT  64
#define XNB 512
#define XSC 48

// gain scratch: per (b,t) 528 floats = [K 16x32][k 16]
__device__ float g_G[(size_t)XNB * XT * 528];

__device__ __forceinline__ void cpa16(void* s, const void* g) {
    unsigned sa = (unsigned)__cvta_generic_to_shared(s);
    asm volatile("cp.async.cg.shared.global [%0], [%1], 16;" :: "r"(sa), "l"(g));
}
__device__ __forceinline__ void cpa_commit() { asm volatile("cp.async.commit_group;"); }
__device__ __forceinline__ void cpa_wait0()  { asm volatile("cp.async.wait_group 0;"); }

__global__ __launch_bounds__(256, 4)
void lqr_kernel(const float* __restrict__ Xi, const float* __restrict__ Qg,
                const float* __restrict__ Pg, const float* __restrict__ Ag,
                const float* __restrict__ Bg, float* __restrict__ out)
{
    __shared__ __align__(16) float sF[32 * 48];
    __shared__ __align__(16) float sV[32 * 36];     // padded rows
    __shared__ __align__(16) float sM[32 * 48];     // backward: V@F ; forward: K dbl-buf
    __shared__ __align__(16) float sQt[48 * 48];
    __shared__ __align__(16) float sQraw[48 * 48];
    __shared__ __align__(16) float scx[64 * 32];
    __shared__ __align__(16) float sKt[16 * 32];
    __shared__ __align__(16) float skt[16];
    __shared__ __align__(16) float sqt[48];
    __shared__ float sv[32];
    __shared__ __align__(16) float sInv[16 * 20];   // stride 20: float4-loadable rows
    __shared__ __align__(16) float sp[48];
    __shared__ float scc[48];                       // cost accumulators

    const int b   = blockIdx.x;
    const int tid = threadIdx.x;
    const float* Qb = Qg + (size_t)b * XT * XSC * XSC;
    const float* Pb = Pg + (size_t)b * XT * XSC;

    // ---- B-phase map: 84 tiles (78 lower-tri + 6 upper uu) split into 168
    //      half-tiles (4 rows x 2 cols per thread)
    int i0B = 0, j0B = 0;
    if (tid < 156) {
        const int tt = tid >> 1;
        int e = tt, r = 0;
        while (e >= r + 1) { e -= r + 1; r++; }
        i0B = r * 4; j0B = e * 4 + (tid & 1) * 2;
    } else if (tid < 168) {
        const int q = (tid - 156) >> 1;            // (8,9)(8,10)(8,11)(9,10)(9,11)(10,11)
        const int rt = (q < 3) ? 8 : ((q < 5) ? 9 : 10);
        const int ct = (q < 3) ? (9 + q) : ((q < 5) ? (7 + q) : 11);
        i0B = rt * 4; j0B = ct * 4 + (tid & 1) * 2;
    }
    // ---- mirror map: 60 strict-upper tiles excluding uu block (threads 64..123)
    int mSrc = 0, mDst = 0;
    if (tid >= 64 && tid < 124) {
        const int myT = tid - 64;
        int cnt = 0;
        for (int rt = 0; rt < 12; rt++)
            for (int ct = rt + 1; ct < 12; ct++) {
                if (rt >= 8 && ct >= 8) continue;
                if (cnt == myT) { mSrc = (ct * 4) * 48 + rt * 4;
                                  mDst = (rt * 4) * 48 + ct * 4; }
                cnt++;
            }
    }

    // ---- setup ----
    for (int e = tid; e < 32 * 48; e += 256) {
        int s = e / 48, j = e % 48;
        sF[e] = (j < 32) ? Ag[s * 32 + j] : Bg[s * 16 + (j - 32)];
    }
    for (int e = tid; e < 32 * 36; e += 256) sV[e] = 0.f;
    if (tid < 32) sv[tid] = 0.f;
    if (tid < 48) scc[tid] = 0.f;
    {   // prefetch Q(T-1), p(T-1)
        const float* qsrc = Qb + (size_t)(XT - 1) * XSC * XSC;
        #pragma unroll
        for (int kk = 0; kk < 3; kk++) { int idx = tid + kk * 256;
            if (idx < 576) cpa16(sQraw + idx * 4, qsrc + idx * 4); }
        if (tid < 12) cpa16(sp + tid * 4, Pb + (size_t)(XT - 1) * XSC + tid * 4);
        cpa_commit();
    }
    __syncthreads();

    // nominal trajectory cx[t] (warp 0)
    if (tid < 32) {
        scx[tid] = Xi[b * 32 + tid];
        for (int t = 1; t < XT; t++) {
            __syncwarp();
            float acc = 0.f;
            #pragma unroll
            for (int jj = 0; jj < 32; jj++) {
                int j = (tid + jj) & 31;
                acc += sF[tid * 48 + j] * scx[(t - 1) * 32 + j];
            }
            scx[t * 32 + tid] = acc;
        }
    }
    __syncthreads();

    // =============== backward Riccati ===============
    for (int t = XT - 1; t >= 0; t--) {
        // A: M = V @ F (V symmetric: row reads), 192 threads, 4x2 tiles
        if (tid < 192) {
            const int s0 = (tid / 24) * 4, j0 = (tid % 24) * 2;
            float a00=0,a01=0,a10=0,a11=0,a20=0,a21=0,a30=0,a31=0;
            #pragma unroll 8
            for (int r = 0; r < 32; r++) {
                const float4 vv = *(const float4*)(sV + r * 36 + s0);
                const float2 ff = *(const float2*)(sF + r * 48 + j0);
                a00 += vv.x*ff.x; a01 += vv.x*ff.y; a10 += vv.y*ff.x; a11 += vv.y*ff.y;
                a20 += vv.z*ff.x; a21 += vv.z*ff.y; a30 += vv.w*ff.x; a31 += vv.w*ff.y;
            }
            *(float2*)(sM + (s0+0)*48 + j0) = make_float2(a00,a01);
            *(float2*)(sM + (s0+1)*48 + j0) = make_float2(a10,a11);
            *(float2*)(sM + (s0+2)*48 + j0) = make_float2(a20,a21);
            *(float2*)(sM + (s0+3)*48 + j0) = make_float2(a30,a31);
        }
        cpa_wait0();
        __syncthreads();                           // Qraw(t), p(t), M ready

        // B: Qt = Qraw + F^T M -- 168 threads, 4x2 half-tiles  ||  qt
        if (tid < 168) {
            const int i0 = i0B, j0 = j0B;
            float2 c0 = *(const float2*)(sQraw + (i0+0)*48 + j0);
            float2 c1 = *(const float2*)(sQraw + (i0+1)*48 + j0);
            float2 c2 = *(const float2*)(sQraw + (i0+2)*48 + j0);
            float2 c3 = *(const float2*)(sQraw + (i0+3)*48 + j0);
            #pragma unroll 8
            for (int s = 0; s < 32; s++) {
                const float4 fa = *(const float4*)(sF + s * 48 + i0);
                const float2 mb = *(const float2*)(sM + s * 48 + j0);
                c0.x += fa.x*mb.x; c0.y += fa.x*mb.y;
                c1.x += fa.y*mb.x; c1.y += fa.y*mb.y;
                c2.x += fa.z*mb.x; c2.y += fa.z*mb.y;
                c3.x += fa.w*mb.x; c3.y += fa.w*mb.y;
            }
            *(float2*)(sQt + (i0+0)*48 + j0) = c0;
            *(float2*)(sQt + (i0+1)*48 + j0) = c1;
            *(float2*)(sQt + (i0+2)*48 + j0) = c2;
            *(float2*)(sQt + (i0+3)*48 + j0) = c3;
        } else if (tid >= 208) {
            const int i = tid - 208;
            float tmp = 0.f;                       // (Qraw_x* · cx)_i
            #pragma unroll
            for (int jj = 0; jj < 32; jj++) {
                int j = (i + jj) & 31;
                tmp += sQraw[i * 48 + j] * scx[t * 32 + j];
            }
            float acc = sp[i] + tmp;
            #pragma unroll
            for (int s = 0; s < 32; s++) acc += sv[s] * sF[s * 48 + i];
            sqt[i] = acc;
            if (i < 32)                            // stage const: cx_i (0.5 tmp + p_i)
                scc[i] += scx[t * 32 + i] * (0.5f * tmp + sp[i]);
        }
        __syncthreads();                           // Qt(lower+uu), qt ready; Qraw free

        // C: prefetch next Q,p  +  warp-0 GJ inverse of Quu  +  mirror upper tiles
        if (t > 0) {
            const float* qsrc = Qb + (size_t)(t - 1) * XSC * XSC;
            #pragma unroll
            for (int kk = 0; kk < 3; kk++) { int idx = tid + kk * 256;
                if (idx < 576) cpa16(sQraw + idx * 4, qsrc + idx * 4); }
            if (tid < 12) cpa16(sp + tid * 4, Pb + (size_t)(t - 1) * XSC + tid * 4);
            cpa_commit();
        }
        if (tid < 32) {
            const int lane = tid, col = lane & 15;
            float creg[16];
            if (lane < 16) {
                #pragma unroll
                for (int i2 = 0; i2 < 16; i2++) creg[i2] = sQt[(32+i2)*48 + 32 + lane];
            } else {
                #pragma unroll
                for (int i2 = 0; i2 < 16; i2++) creg[i2] = (i2 == col) ? 1.f : 0.f;
            }
            #pragma unroll
            for (int k = 0; k < 16; k++) {
                const float ck  = __shfl_sync(0xffffffffu, creg[k], k);
                const float piv = 1.0f / ck;
                creg[k] *= piv;
                #pragma unroll
                for (int i2 = 0; i2 < 16; i2++) {
                    if (i2 == k) continue;
                    const float cik = __shfl_sync(0xffffffffu, creg[i2], k);
                    creg[i2] -= cik * creg[k];
                }
            }
            if (lane >= 16) {
                #pragma unroll
                for (int i2 = 0; i2 < 16; i2++) sInv[i2 * 20 + col] = creg[i2];
            }
        } else if (tid >= 64 && tid < 124) {
            // mirror: upper tile <- transpose(lower tile). 4 LDS.128 + 4 STS.128.
            const float4 v0 = *(const float4*)(sQt + mSrc + 0*48);
            const float4 v1 = *(const float4*)(sQt + mSrc + 1*48);
            const float4 v2 = *(const float4*)(sQt + mSrc + 2*48);
            const float4 v3 = *(const float4*)(sQt + mSrc + 3*48);
            *(float4*)(sQt + mDst + 0*48) = make_float4(v0.x, v1.x, v2.x, v3.x);
            *(float4*)(sQt + mDst + 1*48) = make_float4(v0.y, v1.y, v2.y, v3.y);
            *(float4*)(sQt + mDst + 2*48) = make_float4(v0.z, v1.z, v2.z, v3.z);
            *(float4*)(sQt + mDst + 3*48) = make_float4(v0.w, v1.w, v2.w, v3.w);
        }
        __syncthreads();                           // Inv + full symmetric Qt ready

        // D: Kt = -Inv @ Qux -- 64 threads, 4x2 sub-tiles  ||  kt (thr 64-79)
        if (tid < 64) {
            const int a0 = (tid >> 4) * 4;         // 0,4,8,12
            const int i0 = (tid & 15) * 2;         // 0..30
            float2 r0 = {0,0}, r1 = {0,0}, r2 = {0,0}, r3 = {0,0};
            #pragma unroll
            for (int c0 = 0; c0 < 16; c0 += 4) {
                const float4 v0 = *(const float4*)(sInv + (a0+0)*20 + c0);
                const float4 v1 = *(const float4*)(sInv + (a0+1)*20 + c0);
                const float4 v2 = *(const float4*)(sInv + (a0+2)*20 + c0);
                const float4 v3 = *(const float4*)(sInv + (a0+3)*20 + c0);
                const float2 q0 = *(const float2*)(sQt + (32+c0+0)*48 + i0);
                const float2 q1 = *(const float2*)(sQt + (32+c0+1)*48 + i0);
                const float2 q2 = *(const float2*)(sQt + (32+c0+2)*48 + i0);
                const float2 q3 = *(const float2*)(sQt + (32+c0+3)*48 + i0);
                r0.x += v0.x*q0.x + v0.y*q1.x + v0.z*q2.x + v0.w*q3.x;
                r0.y += v0.x*q0.y + v0.y*q1.y + v0.z*q2.y + v0.w*q3.y;
                r1.x += v1.x*q0.x + v1.y*q1.x + v1.z*q2.x + v1.w*q3.x;
                r1.y += v1.x*q0.y + v1.y*q1.y + v1.z*q2.y + v1.w*q3.y;
                r2.x += v2.x*q0.x + v2.y*q1.x + v2.z*q2.x + v2.w*q3.x;
                r2.y += v2.x*q0.y + v2.y*q1.y + v2.z*q2.y + v2.w*q3.y;
                r3.x += v3.x*q0.x + v3.y*q1.x + v3.z*q2.x + v3.w*q3.x;
                r3.y += v3.x*q0.y + v3.y*q1.y + v3.z*q2.y + v3.w*q3.y;
            }
            *(float2*)(sKt + (a0+0)*32 + i0) = make_float2(-r0.x,-r0.y);
            *(float2*)(sKt + (a0+1)*32 + i0) = make_float2(-r1.x,-r1.y);
            *(float2*)(sKt + (a0+2)*32 + i0) = make_float2(-r2.x,-r2.y);
            *(float2*)(sKt + (a0+3)*32 + i0) = make_float2(-r3.x,-r3.y);
        } else if (tid < 80) {
            const int a = tid - 64;
            float acc = 0.f;
            #pragma unroll
            for (int cc = 0; cc < 16; cc++) {
                int c = (a + cc) & 15;
                acc += sInv[a*20 + c] * sqt[32 + c];
            }
            skt[a] = -acc;
            scc[32 + a] += -0.5f * sqt[32 + a] * acc;   // 0.5 * qu_a * kt_a
        }
        __syncthreads();                           // Kt, kt ready

        // E: Vn = Qxx + Qxu Kt -- 128 threads, 4x2  ||  vn (128-159)  ||  gains (160+)
        if (tid < 128) {
            const int i0 = (tid >> 4) * 4;         // 8 row-tiles
            const int j0 = (tid & 15) * 2;         // 16 col-pairs
            float2 v0 = *(const float2*)(sQt + (i0+0)*48 + j0);
            float2 v1 = *(const float2*)(sQt + (i0+1)*48 + j0);
            float2 v2 = *(const float2*)(sQt + (i0+2)*48 + j0);
            float2 v3 = *(const float2*)(sQt + (i0+3)*48 + j0);
            #pragma unroll
            for (int ch = 0; ch < 4; ch++) {
                const int c0 = ((ch + (tid >> 4)) & 3) * 4;  // rotate: spread banks
                const float4 a0v = *(const float4*)(sQt + (i0+0)*48 + 32 + c0);
                const float4 a1v = *(const float4*)(sQt + (i0+1)*48 + 32 + c0);
                const float4 a2v = *(const float4*)(sQt + (i0+2)*48 + 32 + c0);
                const float4 a3v = *(const float4*)(sQt + (i0+3)*48 + 32 + c0);
                const float2 k0 = *(const float2*)(sKt + (c0+0)*32 + j0);
                const float2 k1 = *(const float2*)(sKt + (c0+1)*32 + j0);
                const float2 k2 = *(const float2*)(sKt + (c0+2)*32 + j0);
                const float2 k3 = *(const float2*)(sKt + (c0+3)*32 + j0);
                v0.x += a0v.x*k0.x + a0v.y*k1.x + a0v.z*k2.x + a0v.w*k3.x;
                v0.y += a0v.x*k0.y + a0v.y*k1.y + a0v.z*k2.y + a0v.w*k3.y;
                v1.x += a1v.x*k0.x + a1v.y*k1.x + a1v.z*k2.x + a1v.w*k3.x;
                v1.y += a1v.x*k0.y + a1v.y*k1.y + a1v.z*k2.y + a1v.w*k3.y;
                v2.x += a2v.x*k0.x + a2v.y*k1.x + a2v.z*k2.x + a2v.w*k3.x;
                v2.y += a2v.x*k0.y + a2v.y*k1.y + a2v.z*k2.y + a2v.w*k3.y;
                v3.x += a3v.x*k0.x + a3v.y*k1.x + a3v.z*k2.x + a3v.w*k3.x;
                v3.y += a3v.x*k0.y + a3v.y*k1.y + a3v.z*k2.y + a3v.w*k3.y;
            }
            *(float2*)(sV + (i0+0)*36 + j0) = v0;
            *(float2*)(sV + (i0+1)*36 + j0) = v1;
            *(float2*)(sV + (i0+2)*36 + j0) = v2;
            *(float2*)(sV + (i0+3)*36 + j0) = v3;
        } else if (tid < 160) {
            const int i = tid - 128;
            float acc = sqt[i];
            #pragma unroll
            for (int aa = 0; aa < 16; aa++) {
                int a = (i + aa) & 15;
                acc += sQt[i*48 + 32 + a] * skt[a];
            }
            sv[i] = acc;
        } else {
            float* gdst = g_G + ((size_t)b * XT + t) * 528;
            #pragma unroll
            for (int e = tid - 160; e < 132; e += 96) {
                float4 val;
                if (e < 128) val = *(const float4*)(sKt + e * 4);
                else         val = *(const float4*)(skt + (e - 128) * 4);
                *(float4*)(gdst + e * 4) = val;
            }
        }
        __syncthreads();                           // V, v ready for next step
    }

    // ---- cost write (idle warp) runs concurrently with forward rollout ----
    if (tid == 128) {
        float c = 0.f;
        #pragma unroll
        for (int i = 0; i < 48; i++) c += scc[i];
        out[(size_t)XNB * XT * XNS + (size_t)XNB * XT * XNC + b] = c;
    }

    // =============== forward rollout: warp 0 only, shuffle-resident state ======
    if (tid < 32) {
        const int lane = tid;
        float* kb0 = sM;
        float* kb1 = sM + 544;
        float* out_x = out;
        float* out_u = out + (size_t)XNB * XT * XNS;
        float x = Xi[b * 32 + lane];
        {
            const float* src = g_G + (size_t)b * XT * 528;
            #pragma unroll
            for (int kk = 0; kk < 5; kk++) {
                int e = lane + kk * 32;
                if (e < 132) cpa16(kb0 + e * 4, src + e * 4);
            }
            cpa_commit();
        }
        int pb = 0;
        for (int t = 0; t < XT; t++) {
            cpa_wait0();
            __syncwarp();
            const float* kc = pb ? kb1 : kb0;
            const float d = x - scx[t * 32 + lane];
            float acc = 0.f;
            #pragma unroll
            for (int jj = 0; jj < 32; jj++) {
                int j = (lane + jj) & 31;
                float dj = __shfl_sync(0xffffffffu, d, j);
                if (lane < 16) acc += kc[lane * 32 + j] * dj;
            }
            float u = 0.f;
            if (lane < 16) {
                u = acc + kc[512 + lane];
                out_u[((size_t)b * XT + t) * XNC + lane] = u;
            }
            out_x[((size_t)b * XT + t) * XNS + lane] = x;
            if (t + 1 < XT) {
                const float* src = g_G + ((size_t)b * XT + t + 1) * 528;
                float* kn = pb ? kb0 : kb1;
                #pragma unroll
                for (int kk = 0; kk < 5; kk++) {
                    int e = lane + kk * 32;
                    if (e < 132) cpa16(kn + e * 4, src + e * 4);
                }
                cpa_commit();
            }
            float xn = 0.f, xn2 = 0.f;
            #pragma unroll
            for (int jj = 0; jj < 32; jj++) {
                int j = (lane + jj) & 31;
                float xj = __shfl_sync(0xffffffffu, x, j);
                if (jj & 1) xn2 += sF[lane * 48 + j] * xj;
                else        xn  += sF[lane * 48 + j] * xj;
            }
            #pragma unroll
            for (int aa = 0; aa < 16; aa++) {
                int a2 = (lane + aa) & 15;
                float ua = __shfl_sync(0xffffffffu, u, a2);
                if (aa & 1) xn2 += sF[lane * 48 + 32 + a2] * ua;
                else        xn  += sF[lane * 48 + 32 + a2] * ua;
            }
            x = xn + xn2;
            pb ^= 1;
        }
    }
}

extern "C" void kernel_launch(void* const* d_in, const int* in_sizes, int n_in,
                              void* d_out, int out_size) {
    const float* x_init = (const float*)d_in[0];
    const float* Q      = (const float*)d_in[1];
    const float* p      = (const float*)d_in[2];
    const float* A      = (const float*)d_in[3];
    const float* B      = (const float*)d_in[4];
    float* out = (float*)d_out;
    lqr_kernel<<<XNB, 256>>>(x_init, Q, p, A, B, out);
}